// round 7
// baseline (speedup 1.0000x reference)
#include <cuda_runtime.h>
#include <math.h>

#define HH 512
#define WW 1024
#define BATCH 4
#define BW 32
#define BH 8

typedef unsigned long long ull;

// ---------------- packed f32x2 primitives (sm_103a) ----------------
__device__ __forceinline__ ull pack2(float lo, float hi) {
    ull v;
    asm("mov.b64 %0, {%1, %2};" : "=l"(v)
        : "r"(__float_as_uint(lo)), "r"(__float_as_uint(hi)));
    return v;
}
__device__ __forceinline__ void unpack2(ull v, float& lo, float& hi) {
    unsigned a, b;
    asm("mov.b64 {%0, %1}, %2;" : "=r"(a), "=r"(b) : "l"(v));
    lo = __uint_as_float(a);
    hi = __uint_as_float(b);
}
__device__ __forceinline__ ull add2(ull a, ull b) {
    ull d; asm("add.rn.f32x2 %0, %1, %2;" : "=l"(d) : "l"(a), "l"(b)); return d;
}
__device__ __forceinline__ ull sub2(ull a, ull b) {
    ull d; asm("sub.rn.f32x2 %0, %1, %2;" : "=l"(d) : "l"(a), "l"(b)); return d;
}
__device__ __forceinline__ ull mul2(ull a, ull b) {
    ull d; asm("mul.rn.f32x2 %0, %1, %2;" : "=l"(d) : "l"(a), "l"(b)); return d;
}
__device__ __forceinline__ ull fma2(ull a, ull b, ull c) {
    ull d; asm("fma.rn.f32x2 %0, %1, %2, %3;" : "=l"(d) : "l"(a), "l"(b), "l"(c)); return d;
}
// exact IEEE negation of both lanes (sign-bit xor, ALU pipe)
__device__ __forceinline__ ull neg2(ull a) { return a ^ 0x8000000080000000ULL; }

struct dd2 { ull hi, lo; };   // two independent double-word fp32 lanes

// sum of 3 packed products, exact per lane (TwoProd + TwoSum chain)
__device__ __forceinline__ dd2 sum3prod2(ull a0, ull b0, ull a1, ull b1,
                                         ull a2, ull b2) {
    ull p0 = mul2(a0, b0), e0 = fma2(a0, b0, neg2(p0));
    ull p1 = mul2(a1, b1), e1 = fma2(a1, b1, neg2(p1));
    ull p2 = mul2(a2, b2), e2 = fma2(a2, b2, neg2(p2));
    ull s  = add2(p0, p1);
    ull bb = sub2(s, p0);
    ull er1 = add2(sub2(p0, sub2(s, bb)), sub2(p1, bb));
    ull s2  = add2(s, p2);
    ull bb2 = sub2(s2, s);
    ull er2 = add2(sub2(s, sub2(s2, bb2)), sub2(p2, bb2));
    dd2 r;
    r.hi = s2;
    r.lo = add2(add2(add2(e0, e1), e2), add2(er1, er2));
    return r;
}
// exact sum of 3 packed plain values
__device__ __forceinline__ dd2 sum3_2(ull p0, ull p1, ull p2) {
    ull s  = add2(p0, p1);
    ull bb = sub2(s, p0);
    ull er1 = add2(sub2(p0, sub2(s, bb)), sub2(p1, bb));
    ull s2  = add2(s, p2);
    ull bb2 = sub2(s2, s);
    ull er2 = add2(sub2(s, sub2(s2, bb2)), sub2(p2, bb2));
    dd2 r; r.hi = s2; r.lo = add2(er1, er2);
    return r;
}
// exact sum of 3 packed dd values
__device__ __forceinline__ dd2 sum3dd2(dd2 a, dd2 b, dd2 c) {
    ull s  = add2(a.hi, b.hi);
    ull bb = sub2(s, a.hi);
    ull er1 = add2(sub2(a.hi, sub2(s, bb)), sub2(b.hi, bb));
    ull s2  = add2(s, c.hi);
    ull bb2 = sub2(s2, s);
    ull er2 = add2(sub2(s, sub2(s2, bb2)), sub2(c.hi, bb2));
    dd2 r;
    r.hi = s2;
    r.lo = add2(add2(add2(a.lo, b.lo), c.lo), add2(er1, er2));
    return r;
}
// dd += packed plain value, exact
__device__ __forceinline__ dd2 ddaddf2(dd2 a, ull p) {
    ull s  = add2(a.hi, p);
    ull bb = sub2(s, a.hi);
    ull er = add2(sub2(a.hi, sub2(s, bb)), sub2(p, bb));
    dd2 r; r.hi = s; r.lo = add2(a.lo, er);
    return r;
}
// relaxed dd multiply (drops lo*lo), packed
__device__ __forceinline__ dd2 ddmul2(dd2 a, dd2 b) {
    ull p = mul2(a.hi, b.hi);
    ull e = fma2(a.hi, b.hi, neg2(p));
    e = fma2(a.hi, b.lo, e);
    e = fma2(a.lo, b.hi, e);
    dd2 r; r.hi = p; r.lo = e;
    return r;
}
// cofactor a*b - c*d per lane, exact hi-difference
__device__ __forceinline__ dd2 ddcof2(dd2 a, dd2 b, dd2 c, dd2 d) {
    dd2 p = ddmul2(a, b);
    dd2 q = ddmul2(c, d);
    ull s  = sub2(p.hi, q.hi);
    ull bb = sub2(s, p.hi);
    ull er = add2(sub2(p.hi, sub2(s, bb)), sub2(neg2(q.hi), bb));
    dd2 r; r.hi = s; r.lo = add2(er, sub2(p.lo, q.lo));
    return r;
}

// ---------------- scalar helpers (z pipeline, md2, normalize) --------------
__device__ __forceinline__ float2 sum3(float p0, float p1, float p2) {
    float s  = __fadd_rn(p0, p1);
    float bb = __fsub_rn(s, p0);
    float er1 = __fadd_rn(__fsub_rn(p0, __fsub_rn(s, bb)), __fsub_rn(p1, bb));
    float s2  = __fadd_rn(s, p2);
    float bb2 = __fsub_rn(s2, s);
    float er2 = __fadd_rn(__fsub_rn(s, __fsub_rn(s2, bb2)), __fsub_rn(p2, bb2));
    return make_float2(s2, __fadd_rn(er1, er2));
}
__device__ __forceinline__ float2 sum3dd(float2 a, float2 b, float2 c) {
    float s  = __fadd_rn(a.x, b.x);
    float bb = __fsub_rn(s, a.x);
    float er1 = __fadd_rn(__fsub_rn(a.x, __fsub_rn(s, bb)), __fsub_rn(b.x, bb));
    float s2  = __fadd_rn(s, c.x);
    float bb2 = __fsub_rn(s2, s);
    float er2 = __fadd_rn(__fsub_rn(s, __fsub_rn(s2, bb2)), __fsub_rn(c.x, bb2));
    float lo = __fadd_rn(__fadd_rn(__fadd_rn(a.y, b.y), c.y), __fadd_rn(er1, er2));
    return make_float2(s2, lo);
}
__device__ __forceinline__ float2 ddmul_s(float2 a, float2 b) {
    float p = __fmul_rn(a.x, b.x);
    float e = fmaf(a.x, b.x, -p);
    e = fmaf(a.x, b.y, e);
    e = fmaf(a.y, b.x, e);
    return make_float2(p, e);
}

// ---------------- ray tables (sin/cos in double, rounded to fp32) ----------
__device__ float g_st[WW];
__device__ float g_ct[WW];
__device__ float g_sp[HH];
__device__ float g_cp[HH];

__global__ void rays_kernel() {
    int t = blockIdx.x * blockDim.x + threadIdx.x;
    const float PI_F = 3.14159265358979323846f;   // fl32(pi)
    if (t < WW) {
        float jn = __fmul_rn((float)t + 0.5f, 1.0f / (float)WW);
        float th = __fsub_rn(__fmul_rn(jn, __fmul_rn(2.0f, PI_F)), PI_F);
        double thd = (double)th;
        g_st[t] = (float)sin(thd);
        g_ct[t] = (float)cos(thd);
    } else if (t < WW + HH) {
        int i = t - WW;
        float in_ = __fmul_rn((float)i + 0.5f, 1.0f / (float)HH);
        float ph = __fsub_rn(0.5f * PI_F, __fmul_rn(in_, PI_F));
        double phd = (double)ph;
        g_sp[i] = (float)sin(phd);
        g_cp[i] = (float)cos(phd);
    }
}

// packed pipelines: P0=(xx,xy) P1=(xz,yy) P2=(yz,zz) P3=(x,y); z is scalar
__global__ __launch_bounds__(BW * BH)
void normals_kernel(const float* __restrict__ depth, float* __restrict__ out) {
    __shared__ float4 pts[BH + 2][BW + 2];
    __shared__ ulonglong2 HsP[4][BH + 2][BW];   // {hi2, lo2} per packed pipeline
    __shared__ float2 Hsz[BH + 2][BW];          // scalar z pipeline

    const int bb = blockIdx.z;
    const int i0 = blockIdx.y * BH;
    const int j0 = blockIdx.x * BW;
    const int tid = threadIdx.y * BW + threadIdx.x;
    const float* dptr = depth + (size_t)bb * (HH * WW);

    // Phase A: (BH+2)x(BW+2) tile of fp32 3D points, zero-padded.
    for (int t = tid; t < (BH + 2) * (BW + 2); t += BW * BH) {
        int ly = t / (BW + 2);
        int lx = t - ly * (BW + 2);
        int gi = i0 + ly - 1;
        int gj = j0 + lx - 1;
        float4 p = make_float4(0.0f, 0.0f, 0.0f, 0.0f);
        if (gi >= 0 && gi < HH && gj >= 0 && gj < WW) {
            float d  = __ldg(&dptr[(size_t)gi * WW + gj]);
            float st = g_st[gj];
            float ct = g_ct[gj];
            float sp = g_sp[gi];
            float cp = g_cp[gi];
            float x = __fmul_rn(cp, st);
            float z = __fmul_rn(cp, ct);
            p.x = __fmul_rn(d, x);
            p.y = __fmul_rn(d, sp);
            p.z = __fmul_rn(d, z);
        }
        pts[ly][lx] = p;
    }
    __syncthreads();

    // Phase B: exact horizontal 3-window sums, packed 2 quantities per op.
    for (int t = tid; t < (BH + 2) * BW; t += BW * BH) {
        int ly = t / BW;
        int lx = t - ly * BW;
        float4 p0 = pts[ly][lx];
        float4 p1 = pts[ly][lx + 1];
        float4 p2 = pts[ly][lx + 2];

        ull xx0 = pack2(p0.x, p0.x), xy0 = pack2(p0.x, p0.y);
        ull zy0 = pack2(p0.z, p0.y), yz0 = pack2(p0.y, p0.z), zz0 = pack2(p0.z, p0.z);
        ull xx1 = pack2(p1.x, p1.x), xy1 = pack2(p1.x, p1.y);
        ull zy1 = pack2(p1.z, p1.y), yz1 = pack2(p1.y, p1.z), zz1 = pack2(p1.z, p1.z);
        ull xx2 = pack2(p2.x, p2.x), xy2 = pack2(p2.x, p2.y);
        ull zy2 = pack2(p2.z, p2.y), yz2 = pack2(p2.y, p2.z), zz2 = pack2(p2.z, p2.z);

        dd2 H0 = sum3prod2(xx0, xy0, xx1, xy1, xx2, xy2);  // (xx, xy)
        dd2 H1 = sum3prod2(xy0, zy0, xy1, zy1, xy2, zy2);  // (xz, yy)
        dd2 H2 = sum3prod2(yz0, zz0, yz1, zz1, yz2, zz2);  // (yz, zz)
        dd2 H3 = sum3_2(xy0, xy1, xy2);                    // (x, y)
        float2 Hz = sum3(p0.z, p1.z, p2.z);                // z

        HsP[0][ly][lx] = make_ulonglong2(H0.hi, H0.lo);
        HsP[1][ly][lx] = make_ulonglong2(H1.hi, H1.lo);
        HsP[2][ly][lx] = make_ulonglong2(H2.hi, H2.lo);
        HsP[3][ly][lx] = make_ulonglong2(H3.hi, H3.lo);
        Hsz[ly][lx] = Hz;
    }
    __syncthreads();

    // Phase C: exact vertical 3-sums -> packed dd G, b; packed adjugate solve.
    const int ty = threadIdx.y;
    const int tx = threadIdx.x;

    dd2 V[4];
#pragma unroll
    for (int q = 0; q < 4; q++) {
        ulonglong2 r0 = HsP[q][ty][tx];
        ulonglong2 r1 = HsP[q][ty + 1][tx];
        ulonglong2 r2 = HsP[q][ty + 2][tx];
        dd2 a; a.hi = r0.x; a.lo = r0.y;
        dd2 b; b.hi = r1.x; b.lo = r1.y;
        dd2 c; c.hi = r2.x; c.lo = r2.y;
        V[q] = sum3dd2(a, b, c);
    }
    float2 vz = sum3dd(Hsz[ty][tx], Hsz[ty + 1][tx], Hsz[ty + 2][tx]);  // bz

    // eps on diagonal lanes: ga (V0 lane0), gd (V1 lane1), gf (V2 lane1)
    V[0] = ddaddf2(V[0], pack2(1e-5f, 0.0f));
    V[1] = ddaddf2(V[1], pack2(0.0f, 1e-5f));
    V[2] = ddaddf2(V[2], pack2(0.0f, 1e-5f));

    // unpack to scalars for operand re-packing
    float gah, gbh, gal, gbl; unpack2(V[0].hi, gah, gbh); unpack2(V[0].lo, gal, gbl);
    float gch, gdh, gcl, gdl; unpack2(V[1].hi, gch, gdh); unpack2(V[1].lo, gcl, gdl);
    float geh, gfh, gel, gfl; unpack2(V[2].hi, geh, gfh); unpack2(V[2].lo, gel, gfl);
    float bxh, byh, bxl, byl; unpack2(V[3].hi, bxh, byh); unpack2(V[3].lo, bxl, byl);

    // cofactor operand dd packs
    dd2 Pdc; Pdc.hi = pack2(gdh, gch); Pdc.lo = pack2(gdl, gcl);
    dd2 Pfe; Pfe.hi = pack2(gfh, geh); Pfe.lo = pack2(gfl, gel);
    dd2 Peb; Peb.hi = pack2(geh, gbh); Peb.lo = pack2(gel, gbl);
    dd2 Pef; Pef.hi = pack2(geh, gfh); Pef.lo = pack2(gel, gfl);
    dd2 Pba; Pba.hi = pack2(gbh, gah); Pba.lo = pack2(gbl, gal);
    dd2 Pcc; Pcc.hi = pack2(gch, gch); Pcc.lo = pack2(gcl, gcl);
    dd2 Pcd; Pcd.hi = pack2(gch, gdh); Pcd.lo = pack2(gcl, gdl);
    dd2 Pab; Pab.hi = pack2(gah, gbh); Pab.lo = pack2(gal, gbl);

    dd2 C1 = ddcof2(Pdc, Pfe, Peb, Pef);   // (A00, A01)
    dd2 C2 = ddcof2(Pba, Pef, Pcc, Pdc);   // (A02, A11)
    dd2 C3 = ddcof2(Pba, Pcd, Pab, Peb);   // (A12, A22)

    float A00h, A01h, A00l, A01l; unpack2(C1.hi, A00h, A01h); unpack2(C1.lo, A00l, A01l);
    float A02h, A11h, A02l, A11l; unpack2(C2.hi, A02h, A11h); unpack2(C2.lo, A02l, A11l);
    float A12h, A22h, A12l, A22l; unpack2(C3.hi, A12h, A22h); unpack2(C3.lo, A12l, A22l);

    // (md0, md1) packed: rows (A00,A01,A02) and (A01,A11,A12) dot b
    dd2 Pb_x; Pb_x.hi = pack2(bxh, bxh); Pb_x.lo = pack2(bxl, bxl);
    dd2 Pb_y; Pb_y.hi = pack2(byh, byh); Pb_y.lo = pack2(byl, byl);
    dd2 Pb_z; Pb_z.hi = pack2(vz.x, vz.x); Pb_z.lo = pack2(vz.y, vz.y);
    dd2 PA0111; PA0111.hi = pack2(A01h, A11h); PA0111.lo = pack2(A01l, A11l);
    dd2 PA0212; PA0212.hi = pack2(A02h, A12h); PA0212.lo = pack2(A02l, A12l);

    dd2 md01 = sum3dd2(ddmul2(C1, Pb_x), ddmul2(PA0111, Pb_y), ddmul2(PA0212, Pb_z));

    // md2 scalar: A02*bx + A12*by + A22*bz
    float2 md2 = sum3dd(ddmul_s(make_float2(A02h, A02l), make_float2(bxh, bxl)),
                        ddmul_s(make_float2(A12h, A12l), make_float2(byh, byl)),
                        ddmul_s(make_float2(A22h, A22l), vz));

    float md0h, md1h, md0l, md1l;
    unpack2(md01.hi, md0h, md1h); unpack2(md01.lo, md0l, md1l);
    float m0 = __fadd_rn(md0h, md0l);
    float m1 = __fadd_rn(md1h, md1l);
    float m2 = __fadd_rn(md2.x, md2.y);

    // fp32 normalize (reference semantics)
    float nn = __fmul_rn(m0, m0);
    nn = __fadd_rn(nn, __fmul_rn(m1, m1));
    nn = __fadd_rn(nn, __fmul_rn(m2, m2));
    float norm = sqrtf(nn);
    if (norm == 0.0f) norm = 1e-4f;
    float o0 = __fdiv_rn(-m0, norm);
    float o1 = __fdiv_rn(-m1, norm);
    float o2 = __fdiv_rn(-m2, norm);

    const int gi = i0 + ty;
    const int gj = j0 + tx;
    size_t base = (size_t)bb * 3 * (HH * WW) + (size_t)gi * WW + gj;
    out[base]               = o0;
    out[base +     HH * WW] = o1;
    out[base + 2 * HH * WW] = o2;
}

extern "C" void kernel_launch(void* const* d_in, const int* in_sizes, int n_in,
                              void* d_out, int out_size) {
    const float* depth = (const float*)d_in[0];
    float* out = (float*)d_out;

    rays_kernel<<<(WW + HH + 255) / 256, 256>>>();

    dim3 block(BW, BH, 1);
    dim3 grid(WW / BW, HH / BH, BATCH);
    normals_kernel<<<grid, block>>>(depth, out);
}

// round 8
// speedup vs baseline: 1.0387x; 1.0387x over previous
#include <cuda_runtime.h>
#include <math.h>

#define HH 512
#define WW 1024
#define BATCH 4
#define BW 32
#define BH 8

typedef unsigned long long ull;

// ---------------- packed f32x2 primitives (sm_103a) ----------------
__device__ __forceinline__ ull pack2(float lo, float hi) {
    ull v;
    asm("mov.b64 %0, {%1, %2};" : "=l"(v)
        : "r"(__float_as_uint(lo)), "r"(__float_as_uint(hi)));
    return v;
}
__device__ __forceinline__ void unpack2(ull v, float& lo, float& hi) {
    unsigned a, b;
    asm("mov.b64 {%0, %1}, %2;" : "=r"(a), "=r"(b) : "l"(v));
    lo = __uint_as_float(a);
    hi = __uint_as_float(b);
}
__device__ __forceinline__ ull add2(ull a, ull b) {
    ull d; asm("add.rn.f32x2 %0, %1, %2;" : "=l"(d) : "l"(a), "l"(b)); return d;
}
__device__ __forceinline__ ull sub2(ull a, ull b) {
    ull d; asm("sub.rn.f32x2 %0, %1, %2;" : "=l"(d) : "l"(a), "l"(b)); return d;
}
__device__ __forceinline__ ull mul2(ull a, ull b) {
    ull d; asm("mul.rn.f32x2 %0, %1, %2;" : "=l"(d) : "l"(a), "l"(b)); return d;
}
__device__ __forceinline__ ull fma2(ull a, ull b, ull c) {
    ull d; asm("fma.rn.f32x2 %0, %1, %2, %3;" : "=l"(d) : "l"(a), "l"(b), "l"(c)); return d;
}
__device__ __forceinline__ ull neg2(ull a) { return a ^ 0x8000000080000000ULL; }

struct dd2 { ull hi, lo; };

// sum of 3 packed products, exact per lane (TwoProd + TwoSum chain)
__device__ __forceinline__ dd2 sum3prod2(ull a0, ull b0, ull a1, ull b1,
                                         ull a2, ull b2) {
    ull p0 = mul2(a0, b0), e0 = fma2(a0, b0, neg2(p0));
    ull p1 = mul2(a1, b1), e1 = fma2(a1, b1, neg2(p1));
    ull p2 = mul2(a2, b2), e2 = fma2(a2, b2, neg2(p2));
    ull s  = add2(p0, p1);
    ull bb = sub2(s, p0);
    ull er1 = add2(sub2(p0, sub2(s, bb)), sub2(p1, bb));
    ull s2  = add2(s, p2);
    ull bb2 = sub2(s2, s);
    ull er2 = add2(sub2(s, sub2(s2, bb2)), sub2(p2, bb2));
    dd2 r;
    r.hi = s2;
    r.lo = add2(add2(add2(e0, e1), e2), add2(er1, er2));
    return r;
}
// exact sum of 3 packed plain values
__device__ __forceinline__ dd2 sum3_2(ull p0, ull p1, ull p2) {
    ull s  = add2(p0, p1);
    ull bb = sub2(s, p0);
    ull er1 = add2(sub2(p0, sub2(s, bb)), sub2(p1, bb));
    ull s2  = add2(s, p2);
    ull bb2 = sub2(s2, s);
    ull er2 = add2(sub2(s, sub2(s2, bb2)), sub2(p2, bb2));
    dd2 r; r.hi = s2; r.lo = add2(er1, er2);
    return r;
}
// exact sum of 3 packed dd values
__device__ __forceinline__ dd2 sum3dd2(dd2 a, dd2 b, dd2 c) {
    ull s  = add2(a.hi, b.hi);
    ull bb = sub2(s, a.hi);
    ull er1 = add2(sub2(a.hi, sub2(s, bb)), sub2(b.hi, bb));
    ull s2  = add2(s, c.hi);
    ull bb2 = sub2(s2, s);
    ull er2 = add2(sub2(s, sub2(s2, bb2)), sub2(c.hi, bb2));
    dd2 r;
    r.hi = s2;
    r.lo = add2(add2(add2(a.lo, b.lo), c.lo), add2(er1, er2));
    return r;
}
// dd += packed plain value, exact
__device__ __forceinline__ dd2 ddaddf2(dd2 a, ull p) {
    ull s  = add2(a.hi, p);
    ull bb = sub2(s, a.hi);
    ull er = add2(sub2(a.hi, sub2(s, bb)), sub2(p, bb));
    dd2 r; r.hi = s; r.lo = add2(a.lo, er);
    return r;
}

// ---------------- scalar dd helpers (solve stage, from R6) ----------------
__device__ __forceinline__ float2 sum3(float p0, float p1, float p2) {
    float s  = __fadd_rn(p0, p1);
    float bb = __fsub_rn(s, p0);
    float er1 = __fadd_rn(__fsub_rn(p0, __fsub_rn(s, bb)), __fsub_rn(p1, bb));
    float s2  = __fadd_rn(s, p2);
    float bb2 = __fsub_rn(s2, s);
    float er2 = __fadd_rn(__fsub_rn(s, __fsub_rn(s2, bb2)), __fsub_rn(p2, bb2));
    return make_float2(s2, __fadd_rn(er1, er2));
}
__device__ __forceinline__ float2 sum3dd(float2 a, float2 b, float2 c) {
    float s  = __fadd_rn(a.x, b.x);
    float bb = __fsub_rn(s, a.x);
    float er1 = __fadd_rn(__fsub_rn(a.x, __fsub_rn(s, bb)), __fsub_rn(b.x, bb));
    float s2  = __fadd_rn(s, c.x);
    float bb2 = __fsub_rn(s2, s);
    float er2 = __fadd_rn(__fsub_rn(s, __fsub_rn(s2, bb2)), __fsub_rn(c.x, bb2));
    float lo = __fadd_rn(__fadd_rn(__fadd_rn(a.y, b.y), c.y), __fadd_rn(er1, er2));
    return make_float2(s2, lo);
}
__device__ __forceinline__ float2 ddmul_s(float2 a, float2 b) {
    float p = __fmul_rn(a.x, b.x);
    float e = fmaf(a.x, b.x, -p);
    e = fmaf(a.x, b.y, e);
    e = fmaf(a.y, b.x, e);
    return make_float2(p, e);
}
__device__ __forceinline__ float2 ddcof_s(float2 a, float2 b, float2 c, float2 d) {
    float2 p = ddmul_s(a, b);
    float2 q = ddmul_s(c, d);
    float s  = __fsub_rn(p.x, q.x);
    float bb = __fsub_rn(s, p.x);
    float er = __fadd_rn(__fsub_rn(p.x, __fsub_rn(s, bb)), __fsub_rn(-q.x, bb));
    return make_float2(s, __fadd_rn(er, __fsub_rn(p.y, q.y)));
}

// ---------------- ray tables (sin/cos in double, rounded to fp32) ----------
__device__ float g_st[WW];
__device__ float g_ct[WW];
__device__ float g_sp[HH];
__device__ float g_cp[HH];

__global__ void rays_kernel() {
    int t = blockIdx.x * blockDim.x + threadIdx.x;
    const float PI_F = 3.14159265358979323846f;   // fl32(pi)
    if (t < WW) {
        float jn = __fmul_rn((float)t + 0.5f, 1.0f / (float)WW);
        float th = __fsub_rn(__fmul_rn(jn, __fmul_rn(2.0f, PI_F)), PI_F);
        double thd = (double)th;
        g_st[t] = (float)sin(thd);
        g_ct[t] = (float)cos(thd);
    } else if (t < WW + HH) {
        int i = t - WW;
        float in_ = __fmul_rn((float)i + 0.5f, 1.0f / (float)HH);
        float ph = __fsub_rn(0.5f * PI_F, __fmul_rn(in_, PI_F));
        double phd = (double)ph;
        g_sp[i] = (float)sin(phd);
        g_cp[i] = (float)cos(phd);
    }
}

// packed pipelines: P0=(xx,xy) P1=(xz,yy) P2=(yz,zz) P3=(x,y); z is scalar
__global__ __launch_bounds__(BW * BH)
void normals_kernel(const float* __restrict__ depth, float* __restrict__ out) {
    __shared__ float4 pts[BH + 2][BW + 2];
    __shared__ ulonglong2 HsP[4][BH + 2][BW];   // {hi2, lo2} packed pipelines
    __shared__ float2 Hsz[BH + 2][BW];          // scalar z pipeline

    const int bb = blockIdx.z;
    const int i0 = blockIdx.y * BH;
    const int j0 = blockIdx.x * BW;
    const int tid = threadIdx.y * BW + threadIdx.x;
    const float* dptr = depth + (size_t)bb * (HH * WW);

    // Phase A: (BH+2)x(BW+2) tile of fp32 3D points, zero-padded.
    for (int t = tid; t < (BH + 2) * (BW + 2); t += BW * BH) {
        int ly = t / (BW + 2);
        int lx = t - ly * (BW + 2);
        int gi = i0 + ly - 1;
        int gj = j0 + lx - 1;
        float4 p = make_float4(0.0f, 0.0f, 0.0f, 0.0f);
        if (gi >= 0 && gi < HH && gj >= 0 && gj < WW) {
            float d  = __ldg(&dptr[(size_t)gi * WW + gj]);
            float st = g_st[gj];
            float ct = g_ct[gj];
            float sp = g_sp[gi];
            float cp = g_cp[gi];
            float x = __fmul_rn(cp, st);
            float z = __fmul_rn(cp, ct);
            p.x = __fmul_rn(d, x);
            p.y = __fmul_rn(d, sp);
            p.z = __fmul_rn(d, z);
        }
        pts[ly][lx] = p;
    }
    __syncthreads();

    // Phase B: exact horizontal 3-window sums, packed two quantities per op.
    for (int t = tid; t < (BH + 2) * BW; t += BW * BH) {
        int ly = t / BW;
        int lx = t - ly * BW;
        float4 p0 = pts[ly][lx];
        float4 p1 = pts[ly][lx + 1];
        float4 p2 = pts[ly][lx + 2];

        ull xx0 = pack2(p0.x, p0.x), xy0 = pack2(p0.x, p0.y);
        ull zy0 = pack2(p0.z, p0.y), yz0 = pack2(p0.y, p0.z), zz0 = pack2(p0.z, p0.z);
        ull xx1 = pack2(p1.x, p1.x), xy1 = pack2(p1.x, p1.y);
        ull zy1 = pack2(p1.z, p1.y), yz1 = pack2(p1.y, p1.z), zz1 = pack2(p1.z, p1.z);
        ull xx2 = pack2(p2.x, p2.x), xy2 = pack2(p2.x, p2.y);
        ull zy2 = pack2(p2.z, p2.y), yz2 = pack2(p2.y, p2.z), zz2 = pack2(p2.z, p2.z);

        dd2 H0 = sum3prod2(xx0, xy0, xx1, xy1, xx2, xy2);  // (xx, xy)
        dd2 H1 = sum3prod2(xy0, zy0, xy1, zy1, xy2, zy2);  // (xz, yy)
        dd2 H2 = sum3prod2(yz0, zz0, yz1, zz1, yz2, zz2);  // (yz, zz)
        dd2 H3 = sum3_2(xy0, xy1, xy2);                    // (x, y)
        float2 Hz = sum3(p0.z, p1.z, p2.z);                // z

        HsP[0][ly][lx] = make_ulonglong2(H0.hi, H0.lo);
        HsP[1][ly][lx] = make_ulonglong2(H1.hi, H1.lo);
        HsP[2][ly][lx] = make_ulonglong2(H2.hi, H2.lo);
        HsP[3][ly][lx] = make_ulonglong2(H3.hi, H3.lo);
        Hsz[ly][lx] = Hz;
    }
    __syncthreads();

    // Phase C1: packed vertical 3-sums (lane-parallel, no shuffling).
    const int ty = threadIdx.y;
    const int tx = threadIdx.x;

    dd2 V[4];
#pragma unroll
    for (int q = 0; q < 4; q++) {
        ulonglong2 r0 = HsP[q][ty][tx];
        ulonglong2 r1 = HsP[q][ty + 1][tx];
        ulonglong2 r2 = HsP[q][ty + 2][tx];
        dd2 a; a.hi = r0.x; a.lo = r0.y;
        dd2 b; b.hi = r1.x; b.lo = r1.y;
        dd2 c; c.hi = r2.x; c.lo = r2.y;
        V[q] = sum3dd2(a, b, c);
    }
    float2 vz = sum3dd(Hsz[ty][tx], Hsz[ty + 1][tx], Hsz[ty + 2][tx]);  // bz

    // eps on diagonal lanes: ga (V0.lane0), gd (V1.lane1), gf (V2.lane1)
    V[0] = ddaddf2(V[0], pack2(1e-5f, 0.0f));
    V[1] = ddaddf2(V[1], pack2(0.0f, 1e-5f));
    V[2] = ddaddf2(V[2], pack2(0.0f, 1e-5f));

    // Phase C2: unpack once, then SCALAR dd solve (R6 code — high ILP,
    // no cross-lane repacking).
    float gah, gbh, gal, gbl; unpack2(V[0].hi, gah, gbh); unpack2(V[0].lo, gal, gbl);
    float gch, gdh, gcl, gdl; unpack2(V[1].hi, gch, gdh); unpack2(V[1].lo, gcl, gdl);
    float geh, gfh, gel, gfl; unpack2(V[2].hi, geh, gfh); unpack2(V[2].lo, gel, gfl);
    float bxh, byh, bxl, byl; unpack2(V[3].hi, bxh, byh); unpack2(V[3].lo, bxl, byl);

    float2 ga = make_float2(gah, gal), gb = make_float2(gbh, gbl);
    float2 gc = make_float2(gch, gcl), gd = make_float2(gdh, gdl);
    float2 ge = make_float2(geh, gel), gf = make_float2(gfh, gfl);
    float2 bx = make_float2(bxh, bxl), by = make_float2(byh, byl);

    float2 A00 = ddcof_s(gd, gf, ge, ge);
    float2 A01 = ddcof_s(gc, ge, gb, gf);
    float2 A02 = ddcof_s(gb, ge, gc, gd);
    float2 A11 = ddcof_s(ga, gf, gc, gc);
    float2 A12 = ddcof_s(gb, gc, ga, ge);
    float2 A22 = ddcof_s(ga, gd, gb, gb);

    float2 md0 = sum3dd(ddmul_s(A00, bx), ddmul_s(A01, by), ddmul_s(A02, vz));
    float2 md1 = sum3dd(ddmul_s(A01, bx), ddmul_s(A11, by), ddmul_s(A12, vz));
    float2 md2 = sum3dd(ddmul_s(A02, bx), ddmul_s(A12, by), ddmul_s(A22, vz));

    float m0 = __fadd_rn(md0.x, md0.y);
    float m1 = __fadd_rn(md1.x, md1.y);
    float m2 = __fadd_rn(md2.x, md2.y);

    // fp32 normalize (reference semantics)
    float nn = __fmul_rn(m0, m0);
    nn = __fadd_rn(nn, __fmul_rn(m1, m1));
    nn = __fadd_rn(nn, __fmul_rn(m2, m2));
    float norm = sqrtf(nn);
    if (norm == 0.0f) norm = 1e-4f;
    float o0 = __fdiv_rn(-m0, norm);
    float o1 = __fdiv_rn(-m1, norm);
    float o2 = __fdiv_rn(-m2, norm);

    const int gi = i0 + ty;
    const int gj = j0 + tx;
    size_t base = (size_t)bb * 3 * (HH * WW) + (size_t)gi * WW + gj;
    out[base]               = o0;
    out[base +     HH * WW] = o1;
    out[base + 2 * HH * WW] = o2;
}

extern "C" void kernel_launch(void* const* d_in, const int* in_sizes, int n_in,
                              void* d_out, int out_size) {
    const float* depth = (const float*)d_in[0];
    float* out = (float*)d_out;

    rays_kernel<<<(WW + HH + 255) / 256, 256>>>();

    dim3 block(BW, BH, 1);
    dim3 grid(WW / BW, HH / BH, BATCH);
    normals_kernel<<<grid, block>>>(depth, out);
}

// round 9
// speedup vs baseline: 1.1213x; 1.0795x over previous
#include <cuda_runtime.h>
#include <math.h>

#define HH 512
#define WW 1024
#define BATCH 4
#define BW 32
#define BH 8

typedef unsigned long long ull;

// ---------------- packed f32x2 primitives (sm_103a) ----------------
__device__ __forceinline__ ull pack2(float lo, float hi) {
    ull v;
    asm("mov.b64 %0, {%1, %2};" : "=l"(v)
        : "r"(__float_as_uint(lo)), "r"(__float_as_uint(hi)));
    return v;
}
__device__ __forceinline__ void unpack2(ull v, float& lo, float& hi) {
    unsigned a, b;
    asm("mov.b64 {%0, %1}, %2;" : "=r"(a), "=r"(b) : "l"(v));
    lo = __uint_as_float(a);
    hi = __uint_as_float(b);
}
__device__ __forceinline__ ull add2(ull a, ull b) {
    ull d; asm("add.rn.f32x2 %0, %1, %2;" : "=l"(d) : "l"(a), "l"(b)); return d;
}
__device__ __forceinline__ ull sub2(ull a, ull b) {
    ull d; asm("sub.rn.f32x2 %0, %1, %2;" : "=l"(d) : "l"(a), "l"(b)); return d;
}
__device__ __forceinline__ ull mul2(ull a, ull b) {
    ull d; asm("mul.rn.f32x2 %0, %1, %2;" : "=l"(d) : "l"(a), "l"(b)); return d;
}
__device__ __forceinline__ ull fma2(ull a, ull b, ull c) {
    ull d; asm("fma.rn.f32x2 %0, %1, %2, %3;" : "=l"(d) : "l"(a), "l"(b), "l"(c)); return d;
}
__device__ __forceinline__ ull neg2(ull a) { return a ^ 0x8000000080000000ULL; }

struct dd2 { ull hi, lo; };

// sum of 3 packed products, exact per lane (TwoProd + TwoSum chain)
__device__ __forceinline__ dd2 sum3prod2(ull a0, ull b0, ull a1, ull b1,
                                         ull a2, ull b2) {
    ull p0 = mul2(a0, b0), e0 = fma2(a0, b0, neg2(p0));
    ull p1 = mul2(a1, b1), e1 = fma2(a1, b1, neg2(p1));
    ull p2 = mul2(a2, b2), e2 = fma2(a2, b2, neg2(p2));
    ull s  = add2(p0, p1);
    ull bb = sub2(s, p0);
    ull er1 = add2(sub2(p0, sub2(s, bb)), sub2(p1, bb));
    ull s2  = add2(s, p2);
    ull bb2 = sub2(s2, s);
    ull er2 = add2(sub2(s, sub2(s2, bb2)), sub2(p2, bb2));
    dd2 r;
    r.hi = s2;
    r.lo = add2(add2(add2(e0, e1), e2), add2(er1, er2));
    return r;
}
// exact sum of 3 packed dd values
__device__ __forceinline__ dd2 sum3dd2(dd2 a, dd2 b, dd2 c) {
    ull s  = add2(a.hi, b.hi);
    ull bb = sub2(s, a.hi);
    ull er1 = add2(sub2(a.hi, sub2(s, bb)), sub2(b.hi, bb));
    ull s2  = add2(s, c.hi);
    ull bb2 = sub2(s2, s);
    ull er2 = add2(sub2(s, sub2(s2, bb2)), sub2(c.hi, bb2));
    dd2 r;
    r.hi = s2;
    r.lo = add2(add2(add2(a.lo, b.lo), c.lo), add2(er1, er2));
    return r;
}
// dd += packed plain value, exact
__device__ __forceinline__ dd2 ddaddf2(dd2 a, ull p) {
    ull s  = add2(a.hi, p);
    ull bb = sub2(s, a.hi);
    ull er = add2(sub2(a.hi, sub2(s, bb)), sub2(p, bb));
    dd2 r; r.hi = s; r.lo = add2(a.lo, er);
    return r;
}

// ---------------- scalar dd helpers (solve stage) ----------------
__device__ __forceinline__ float2 sum3dd(float2 a, float2 b, float2 c) {
    float s  = __fadd_rn(a.x, b.x);
    float bb = __fsub_rn(s, a.x);
    float er1 = __fadd_rn(__fsub_rn(a.x, __fsub_rn(s, bb)), __fsub_rn(b.x, bb));
    float s2  = __fadd_rn(s, c.x);
    float bb2 = __fsub_rn(s2, s);
    float er2 = __fadd_rn(__fsub_rn(s, __fsub_rn(s2, bb2)), __fsub_rn(c.x, bb2));
    float lo = __fadd_rn(__fadd_rn(__fadd_rn(a.y, b.y), c.y), __fadd_rn(er1, er2));
    return make_float2(s2, lo);
}
__device__ __forceinline__ float2 ddmul_s(float2 a, float2 b) {
    float p = __fmul_rn(a.x, b.x);
    float e = fmaf(a.x, b.x, -p);
    e = fmaf(a.x, b.y, e);
    e = fmaf(a.y, b.x, e);
    return make_float2(p, e);
}
// dd * plain float (b has no lo limb)
__device__ __forceinline__ float2 ddmul_f(float2 a, float b) {
    float p = __fmul_rn(a.x, b);
    float e = fmaf(a.x, b, -p);
    e = fmaf(a.y, b, e);
    return make_float2(p, e);
}
__device__ __forceinline__ float2 ddcof_s(float2 a, float2 b, float2 c, float2 d) {
    float2 p = ddmul_s(a, b);
    float2 q = ddmul_s(c, d);
    float s  = __fsub_rn(p.x, q.x);
    float bb = __fsub_rn(s, p.x);
    float er = __fadd_rn(__fsub_rn(p.x, __fsub_rn(s, bb)), __fsub_rn(-q.x, bb));
    return make_float2(s, __fadd_rn(er, __fsub_rn(p.y, q.y)));
}

// ---------------- ray tables (sin/cos in double, rounded to fp32) ----------
__device__ float g_st[WW];
__device__ float g_ct[WW];
__device__ float g_sp[HH];
__device__ float g_cp[HH];

__global__ void rays_kernel() {
    int t = blockIdx.x * blockDim.x + threadIdx.x;
    const float PI_F = 3.14159265358979323846f;   // fl32(pi)
    if (t < WW) {
        float jn = __fmul_rn((float)t + 0.5f, 1.0f / (float)WW);
        float th = __fsub_rn(__fmul_rn(jn, __fmul_rn(2.0f, PI_F)), PI_F);
        double thd = (double)th;
        g_st[t] = (float)sin(thd);
        g_ct[t] = (float)cos(thd);
    } else if (t < WW + HH) {
        int i = t - WW;
        float in_ = __fmul_rn((float)i + 0.5f, 1.0f / (float)HH);
        float ph = __fsub_rn(0.5f * PI_F, __fmul_rn(in_, PI_F));
        double phd = (double)ph;
        g_sp[i] = (float)sin(phd);
        g_cp[i] = (float)cos(phd);
    }
}

// packed dd pipelines: P0=(xx,xy) P1=(xz,yy) P2=(yz,zz); b=(x,y) packed fp32 + z fp32
__global__ __launch_bounds__(BW * BH, 6)
void normals_kernel(const float* __restrict__ depth, float* __restrict__ out) {
    __shared__ float4 pts[BH + 2][BW + 2];
    __shared__ ulonglong2 HsP[3][BH + 2][BW];   // {hi2, lo2} dd pipelines
    __shared__ ull HsB[BH + 2][BW];             // packed (x,y) plain sums
    __shared__ float HsZ[BH + 2][BW];           // plain z sums

    const int bb = blockIdx.z;
    const int i0 = blockIdx.y * BH;
    const int j0 = blockIdx.x * BW;
    const int tid = threadIdx.y * BW + threadIdx.x;
    const float* dptr = depth + (size_t)bb * (HH * WW);

    // Phase A: (BH+2)x(BW+2) tile of fp32 3D points, zero-padded.
    for (int t = tid; t < (BH + 2) * (BW + 2); t += BW * BH) {
        int ly = t / (BW + 2);
        int lx = t - ly * (BW + 2);
        int gi = i0 + ly - 1;
        int gj = j0 + lx - 1;
        float4 p = make_float4(0.0f, 0.0f, 0.0f, 0.0f);
        if (gi >= 0 && gi < HH && gj >= 0 && gj < WW) {
            float d  = __ldg(&dptr[(size_t)gi * WW + gj]);
            float st = g_st[gj];
            float ct = g_ct[gj];
            float sp = g_sp[gi];
            float cp = g_cp[gi];
            float x = __fmul_rn(cp, st);
            float z = __fmul_rn(cp, ct);
            p.x = __fmul_rn(d, x);
            p.y = __fmul_rn(d, sp);
            p.z = __fmul_rn(d, z);
        }
        pts[ly][lx] = p;
    }
    __syncthreads();

    // Phase B: horizontal 3-window sums. G products in exact packed dd;
    // b sums in plain fp32 (error contribution ~1e-6 — within budget).
    for (int t = tid; t < (BH + 2) * BW; t += BW * BH) {
        int ly = t / BW;
        int lx = t - ly * BW;
        float4 p0 = pts[ly][lx];
        float4 p1 = pts[ly][lx + 1];
        float4 p2 = pts[ly][lx + 2];

        ull xx0 = pack2(p0.x, p0.x), xy0 = pack2(p0.x, p0.y);
        ull zy0 = pack2(p0.z, p0.y), yz0 = pack2(p0.y, p0.z), zz0 = pack2(p0.z, p0.z);
        ull xx1 = pack2(p1.x, p1.x), xy1 = pack2(p1.x, p1.y);
        ull zy1 = pack2(p1.z, p1.y), yz1 = pack2(p1.y, p1.z), zz1 = pack2(p1.z, p1.z);
        ull xx2 = pack2(p2.x, p2.x), xy2 = pack2(p2.x, p2.y);
        ull zy2 = pack2(p2.z, p2.y), yz2 = pack2(p2.y, p2.z), zz2 = pack2(p2.z, p2.z);

        dd2 H0 = sum3prod2(xx0, xy0, xx1, xy1, xx2, xy2);  // (xx, xy)
        dd2 H1 = sum3prod2(xy0, zy0, xy1, zy1, xy2, zy2);  // (xz, yy)
        dd2 H2 = sum3prod2(yz0, zz0, yz1, zz1, yz2, zz2);  // (yz, zz)

        HsP[0][ly][lx] = make_ulonglong2(H0.hi, H0.lo);
        HsP[1][ly][lx] = make_ulonglong2(H1.hi, H1.lo);
        HsP[2][ly][lx] = make_ulonglong2(H2.hi, H2.lo);
        HsB[ly][lx] = add2(add2(xy0, xy1), xy2);                        // (x, y)
        HsZ[ly][lx] = __fadd_rn(__fadd_rn(p0.z, p1.z), p2.z);           // z
    }
    __syncthreads();

    // Phase C1: packed vertical 3-sums (lane-parallel).
    const int ty = threadIdx.y;
    const int tx = threadIdx.x;

    dd2 V[3];
#pragma unroll
    for (int q = 0; q < 3; q++) {
        ulonglong2 r0 = HsP[q][ty][tx];
        ulonglong2 r1 = HsP[q][ty + 1][tx];
        ulonglong2 r2 = HsP[q][ty + 2][tx];
        dd2 a; a.hi = r0.x; a.lo = r0.y;
        dd2 b; b.hi = r1.x; b.lo = r1.y;
        dd2 c; c.hi = r2.x; c.lo = r2.y;
        V[q] = sum3dd2(a, b, c);
    }
    ull  vb = add2(add2(HsB[ty][tx], HsB[ty + 1][tx]), HsB[ty + 2][tx]);
    float vz = __fadd_rn(__fadd_rn(HsZ[ty][tx], HsZ[ty + 1][tx]), HsZ[ty + 2][tx]);

    // eps on diagonal lanes: ga (V0.lane0), gd (V1.lane1), gf (V2.lane1)
    V[0] = ddaddf2(V[0], pack2(1e-5f, 0.0f));
    V[1] = ddaddf2(V[1], pack2(0.0f, 1e-5f));
    V[2] = ddaddf2(V[2], pack2(0.0f, 1e-5f));

    // Phase C2: unpack once, then SCALAR dd solve (high ILP).
    float gah, gbh, gal, gbl; unpack2(V[0].hi, gah, gbh); unpack2(V[0].lo, gal, gbl);
    float gch, gdh, gcl, gdl; unpack2(V[1].hi, gch, gdh); unpack2(V[1].lo, gcl, gdl);
    float geh, gfh, gel, gfl; unpack2(V[2].hi, geh, gfh); unpack2(V[2].lo, gel, gfl);
    float bx, by; unpack2(vb, bx, by);

    float2 ga = make_float2(gah, gal), gb = make_float2(gbh, gbl);
    float2 gc = make_float2(gch, gcl), gd = make_float2(gdh, gdl);
    float2 ge = make_float2(geh, gel), gf = make_float2(gfh, gfl);

    float2 A00 = ddcof_s(gd, gf, ge, ge);
    float2 A01 = ddcof_s(gc, ge, gb, gf);
    float2 A02 = ddcof_s(gb, ge, gc, gd);
    float2 A11 = ddcof_s(ga, gf, gc, gc);
    float2 A12 = ddcof_s(gb, gc, ga, ge);
    float2 A22 = ddcof_s(ga, gd, gb, gb);

    float2 md0 = sum3dd(ddmul_f(A00, bx), ddmul_f(A01, by), ddmul_f(A02, vz));
    float2 md1 = sum3dd(ddmul_f(A01, bx), ddmul_f(A11, by), ddmul_f(A12, vz));
    float2 md2 = sum3dd(ddmul_f(A02, bx), ddmul_f(A12, by), ddmul_f(A22, vz));

    float m0 = __fadd_rn(md0.x, md0.y);
    float m1 = __fadd_rn(md1.x, md1.y);
    float m2 = __fadd_rn(md2.x, md2.y);

    // fp32 normalize (reference semantics)
    float nn = __fmul_rn(m0, m0);
    nn = __fadd_rn(nn, __fmul_rn(m1, m1));
    nn = __fadd_rn(nn, __fmul_rn(m2, m2));
    float norm = sqrtf(nn);
    if (norm == 0.0f) norm = 1e-4f;
    float o0 = __fdiv_rn(-m0, norm);
    float o1 = __fdiv_rn(-m1, norm);
    float o2 = __fdiv_rn(-m2, norm);

    const int gi = i0 + ty;
    const int gj = j0 + tx;
    size_t base = (size_t)bb * 3 * (HH * WW) + (size_t)gi * WW + gj;
    out[base]               = o0;
    out[base +     HH * WW] = o1;
    out[base + 2 * HH * WW] = o2;
}

extern "C" void kernel_launch(void* const* d_in, const int* in_sizes, int n_in,
                              void* d_out, int out_size) {
    const float* depth = (const float*)d_in[0];
    float* out = (float*)d_out;

    rays_kernel<<<(WW + HH + 255) / 256, 256>>>();

    dim3 block(BW, BH, 1);
    dim3 grid(WW / BW, HH / BH, BATCH);
    normals_kernel<<<grid, block>>>(depth, out);
}

// round 10
// speedup vs baseline: 1.1850x; 1.0568x over previous
#include <cuda_runtime.h>
#include <math.h>

#define HH 512
#define WW 1024
#define BATCH 4
#define BW 32
#define TH 8     // pixel tile height per block
#define TY 4     // thread rows (2 pixels each)

typedef unsigned long long ull;

// ---------------- packed f32x2 primitives (sm_103a) ----------------
__device__ __forceinline__ ull pack2(float lo, float hi) {
    ull v;
    asm("mov.b64 %0, {%1, %2};" : "=l"(v)
        : "r"(__float_as_uint(lo)), "r"(__float_as_uint(hi)));
    return v;
}
__device__ __forceinline__ void unpack2(ull v, float& lo, float& hi) {
    unsigned a, b;
    asm("mov.b64 {%0, %1}, %2;" : "=r"(a), "=r"(b) : "l"(v));
    lo = __uint_as_float(a);
    hi = __uint_as_float(b);
}
__device__ __forceinline__ ull add2(ull a, ull b) {
    ull d; asm("add.rn.f32x2 %0, %1, %2;" : "=l"(d) : "l"(a), "l"(b)); return d;
}
__device__ __forceinline__ ull sub2(ull a, ull b) {
    ull d; asm("sub.rn.f32x2 %0, %1, %2;" : "=l"(d) : "l"(a), "l"(b)); return d;
}
__device__ __forceinline__ ull mul2(ull a, ull b) {
    ull d; asm("mul.rn.f32x2 %0, %1, %2;" : "=l"(d) : "l"(a), "l"(b)); return d;
}
__device__ __forceinline__ ull fma2(ull a, ull b, ull c) {
    ull d; asm("fma.rn.f32x2 %0, %1, %2, %3;" : "=l"(d) : "l"(a), "l"(b), "l"(c)); return d;
}
__device__ __forceinline__ ull neg2(ull a) { return a ^ 0x8000000080000000ULL; }

struct dd2 { ull hi, lo; };

// sum of 3 packed products, exact per lane (TwoProd + TwoSum chain)
__device__ __forceinline__ dd2 sum3prod2(ull a0, ull b0, ull a1, ull b1,
                                         ull a2, ull b2) {
    ull p0 = mul2(a0, b0), e0 = fma2(a0, b0, neg2(p0));
    ull p1 = mul2(a1, b1), e1 = fma2(a1, b1, neg2(p1));
    ull p2 = mul2(a2, b2), e2 = fma2(a2, b2, neg2(p2));
    ull s  = add2(p0, p1);
    ull bb = sub2(s, p0);
    ull er1 = add2(sub2(p0, sub2(s, bb)), sub2(p1, bb));
    ull s2  = add2(s, p2);
    ull bb2 = sub2(s2, s);
    ull er2 = add2(sub2(s, sub2(s2, bb2)), sub2(p2, bb2));
    dd2 r;
    r.hi = s2;
    r.lo = add2(add2(add2(e0, e1), e2), add2(er1, er2));
    return r;
}
// exact packed dd + dd
__device__ __forceinline__ dd2 ddadd2(dd2 a, dd2 b) {
    ull s  = add2(a.hi, b.hi);
    ull bb = sub2(s, a.hi);
    ull er = add2(sub2(a.hi, sub2(s, bb)), sub2(b.hi, bb));
    dd2 r; r.hi = s; r.lo = add2(add2(a.lo, b.lo), er);
    return r;
}
// dd += packed plain value, exact
__device__ __forceinline__ dd2 ddaddf2(dd2 a, ull p) {
    ull s  = add2(a.hi, p);
    ull bb = sub2(s, a.hi);
    ull er = add2(sub2(a.hi, sub2(s, bb)), sub2(p, bb));
    dd2 r; r.hi = s; r.lo = add2(a.lo, er);
    return r;
}
// relaxed packed dd multiply (drops lo*lo)
__device__ __forceinline__ dd2 ddmul2(dd2 a, dd2 b) {
    ull p = mul2(a.hi, b.hi);
    ull e = fma2(a.hi, b.hi, neg2(p));
    e = fma2(a.hi, b.lo, e);
    e = fma2(a.lo, b.hi, e);
    dd2 r; r.hi = p; r.lo = e;
    return r;
}
// packed dd * packed plain
__device__ __forceinline__ dd2 ddmulf2(dd2 a, ull b) {
    ull p = mul2(a.hi, b);
    ull e = fma2(a.hi, b, neg2(p));
    e = fma2(a.lo, b, e);
    dd2 r; r.hi = p; r.lo = e;
    return r;
}
// packed cofactor a*b - c*d, exact hi-difference
__device__ __forceinline__ dd2 ddcof2(dd2 a, dd2 b, dd2 c, dd2 d) {
    dd2 p = ddmul2(a, b);
    dd2 q = ddmul2(c, d);
    ull s  = sub2(p.hi, q.hi);
    ull bb = sub2(s, p.hi);
    ull er = add2(sub2(p.hi, sub2(s, bb)), sub2(neg2(q.hi), bb));
    dd2 r; r.hi = s; r.lo = add2(er, sub2(p.lo, q.lo));
    return r;
}
// exact packed 3-sum of dd values
__device__ __forceinline__ dd2 sum3dd2(dd2 a, dd2 b, dd2 c) {
    ull s  = add2(a.hi, b.hi);
    ull bb = sub2(s, a.hi);
    ull er1 = add2(sub2(a.hi, sub2(s, bb)), sub2(b.hi, bb));
    ull s2  = add2(s, c.hi);
    ull bb2 = sub2(s2, s);
    ull er2 = add2(sub2(s, sub2(s2, bb2)), sub2(c.hi, bb2));
    dd2 r;
    r.hi = s2;
    r.lo = add2(add2(add2(a.lo, b.lo), c.lo), add2(er1, er2));
    return r;
}

// ---------------- ray tables (sin/cos in double, rounded to fp32) ----------
__device__ float g_st[WW];
__device__ float g_ct[WW];
__device__ float g_sp[HH];
__device__ float g_cp[HH];

__global__ void rays_kernel() {
    int t = blockIdx.x * blockDim.x + threadIdx.x;
    const float PI_F = 3.14159265358979323846f;   // fl32(pi)
    if (t < WW) {
        float jn = __fmul_rn((float)t + 0.5f, 1.0f / (float)WW);
        float th = __fsub_rn(__fmul_rn(jn, __fmul_rn(2.0f, PI_F)), PI_F);
        double thd = (double)th;
        g_st[t] = (float)sin(thd);
        g_ct[t] = (float)cos(thd);
    } else if (t < WW + HH) {
        int i = t - WW;
        float in_ = __fmul_rn((float)i + 0.5f, 1.0f / (float)HH);
        float ph = __fsub_rn(0.5f * PI_F, __fmul_rn(in_, PI_F));
        double phd = (double)ph;
        g_sp[i] = (float)sin(phd);
        g_cp[i] = (float)cos(phd);
    }
}

// Phase B quantity-packed pipelines: P0=(xx,xy) P1=(xz,yy) P2=(yz,zz);
// b = (x,y) packed plain + z plain. Phase C2 repacks lanes as pixel pairs.
__global__ __launch_bounds__(BW * TY, 9)
void normals_kernel(const float* __restrict__ depth, float* __restrict__ out) {
    __shared__ float4 pts[TH + 2][BW + 2];
    __shared__ ulonglong2 HsP[3][TH + 2][BW];
    __shared__ ull HsB[TH + 2][BW];
    __shared__ float HsZ[TH + 2][BW];

    const int bb = blockIdx.z;
    const int i0 = blockIdx.y * TH;
    const int j0 = blockIdx.x * BW;
    const int tid = threadIdx.y * BW + threadIdx.x;
    const int NT = BW * TY;
    const float* dptr = depth + (size_t)bb * (HH * WW);

    // Phase A: (TH+2)x(BW+2) tile of fp32 3D points, zero-padded.
    for (int t = tid; t < (TH + 2) * (BW + 2); t += NT) {
        int ly = t / (BW + 2);
        int lx = t - ly * (BW + 2);
        int gi = i0 + ly - 1;
        int gj = j0 + lx - 1;
        float4 p = make_float4(0.0f, 0.0f, 0.0f, 0.0f);
        if (gi >= 0 && gi < HH && gj >= 0 && gj < WW) {
            float d  = __ldg(&dptr[(size_t)gi * WW + gj]);
            float st = g_st[gj];
            float ct = g_ct[gj];
            float sp = g_sp[gi];
            float cp = g_cp[gi];
            float x = __fmul_rn(cp, st);
            float z = __fmul_rn(cp, ct);
            p.x = __fmul_rn(d, x);
            p.y = __fmul_rn(d, sp);
            p.z = __fmul_rn(d, z);
        }
        pts[ly][lx] = p;
    }
    __syncthreads();

    // Phase B: exact horizontal 3-window sums, quantity-packed.
    for (int t = tid; t < (TH + 2) * BW; t += NT) {
        int ly = t / BW;
        int lx = t - ly * BW;
        float4 p0 = pts[ly][lx];
        float4 p1 = pts[ly][lx + 1];
        float4 p2 = pts[ly][lx + 2];

        ull xx0 = pack2(p0.x, p0.x), xy0 = pack2(p0.x, p0.y);
        ull zy0 = pack2(p0.z, p0.y), yz0 = pack2(p0.y, p0.z), zz0 = pack2(p0.z, p0.z);
        ull xx1 = pack2(p1.x, p1.x), xy1 = pack2(p1.x, p1.y);
        ull zy1 = pack2(p1.z, p1.y), yz1 = pack2(p1.y, p1.z), zz1 = pack2(p1.z, p1.z);
        ull xx2 = pack2(p2.x, p2.x), xy2 = pack2(p2.x, p2.y);
        ull zy2 = pack2(p2.z, p2.y), yz2 = pack2(p2.y, p2.z), zz2 = pack2(p2.z, p2.z);

        dd2 H0 = sum3prod2(xx0, xy0, xx1, xy1, xx2, xy2);  // (xx, xy)
        dd2 H1 = sum3prod2(xy0, zy0, xy1, zy1, xy2, zy2);  // (xz, yy)
        dd2 H2 = sum3prod2(yz0, zz0, yz1, zz1, yz2, zz2);  // (yz, zz)

        HsP[0][ly][lx] = make_ulonglong2(H0.hi, H0.lo);
        HsP[1][ly][lx] = make_ulonglong2(H1.hi, H1.lo);
        HsP[2][ly][lx] = make_ulonglong2(H2.hi, H2.lo);
        HsB[ly][lx] = add2(add2(xy0, xy1), xy2);                 // (x, y)
        HsZ[ly][lx] = __fadd_rn(__fadd_rn(p0.z, p1.z), p2.z);    // z
    }
    __syncthreads();

    // Phase C1: vertical sums for TWO adjacent pixels per thread, sharing the
    // middle partial t = h[r] + h[r+1] (exact dd adds; grouping change is
    // within the 2^-45 exactness budget).
    const int ty = threadIdx.y;
    const int tx = threadIdx.x;
    const int r0 = 2 * ty;        // padded top row of the pair's window

    dd2 Vp0[3], Vp1[3];           // quantity-packed per pixel
#pragma unroll
    for (int q = 0; q < 3; q++) {
        ulonglong2 h0 = HsP[q][r0][tx];
        ulonglong2 h1 = HsP[q][r0 + 1][tx];
        ulonglong2 h2 = HsP[q][r0 + 2][tx];
        ulonglong2 h3 = HsP[q][r0 + 3][tx];
        dd2 a; a.hi = h0.x; a.lo = h0.y;
        dd2 b; b.hi = h1.x; b.lo = h1.y;
        dd2 c; c.hi = h2.x; c.lo = h2.y;
        dd2 d; d.hi = h3.x; d.lo = h3.y;
        dd2 t = ddadd2(b, c);
        Vp0[q] = ddadd2(t, a);
        Vp1[q] = ddadd2(t, d);
    }
    ull  B0 = HsB[r0][tx], B1 = HsB[r0 + 1][tx];
    ull  B2 = HsB[r0 + 2][tx], B3 = HsB[r0 + 3][tx];
    ull  tB = add2(B1, B2);
    ull  vb0 = add2(tB, B0);
    ull  vb1 = add2(tB, B3);
    float z0 = HsZ[r0][tx], z1 = HsZ[r0 + 1][tx];
    float z2 = HsZ[r0 + 2][tx], z3 = HsZ[r0 + 3][tx];
    float tZ = __fadd_rn(z1, z2);
    float vz0 = __fadd_rn(tZ, z0);
    float vz1 = __fadd_rn(tZ, z3);

    // Lane conversion: quantity-packed -> pixel-packed (lane0=pixel0, lane1=pixel1)
    float a0h, b0h, a0l, b0l; unpack2(Vp0[0].hi, a0h, b0h); unpack2(Vp0[0].lo, a0l, b0l);
    float c0h, d0h, c0l, d0l; unpack2(Vp0[1].hi, c0h, d0h); unpack2(Vp0[1].lo, c0l, d0l);
    float e0h, f0h, e0l, f0l; unpack2(Vp0[2].hi, e0h, f0h); unpack2(Vp0[2].lo, e0l, f0l);
    float a1h, b1h, a1l, b1l; unpack2(Vp1[0].hi, a1h, b1h); unpack2(Vp1[0].lo, a1l, b1l);
    float c1h, d1h, c1l, d1l; unpack2(Vp1[1].hi, c1h, d1h); unpack2(Vp1[1].lo, c1l, d1l);
    float e1h, f1h, e1l, f1l; unpack2(Vp1[2].hi, e1h, f1h); unpack2(Vp1[2].lo, e1l, f1l);
    float bx0, by0; unpack2(vb0, bx0, by0);
    float bx1, by1; unpack2(vb1, bx1, by1);

    dd2 Ga; Ga.hi = pack2(a0h, a1h); Ga.lo = pack2(a0l, a1l);
    dd2 Gb; Gb.hi = pack2(b0h, b1h); Gb.lo = pack2(b0l, b1l);
    dd2 Gc; Gc.hi = pack2(c0h, c1h); Gc.lo = pack2(c0l, c1l);
    dd2 Gd; Gd.hi = pack2(d0h, d1h); Gd.lo = pack2(d0l, d1l);
    dd2 Ge; Ge.hi = pack2(e0h, e1h); Ge.lo = pack2(e0l, e1l);
    dd2 Gf; Gf.hi = pack2(f0h, f1h); Gf.lo = pack2(f0l, f1l);
    ull Bx = pack2(bx0, bx1);
    ull By = pack2(by0, by1);
    ull Bz = pack2(vz0, vz1);

    const ull EPS2 = pack2(1e-5f, 1e-5f);
    Ga = ddaddf2(Ga, EPS2);
    Gd = ddaddf2(Gd, EPS2);
    Gf = ddaddf2(Gf, EPS2);

    // Phase C2: packed symmetric adjugate solve — both pixels per instruction,
    // per-lane IEEE ops identical to the scalar version.
    dd2 A00 = ddcof2(Gd, Gf, Ge, Ge);
    dd2 A01 = ddcof2(Gc, Ge, Gb, Gf);
    dd2 A02 = ddcof2(Gb, Ge, Gc, Gd);
    dd2 A11 = ddcof2(Ga, Gf, Gc, Gc);
    dd2 A12 = ddcof2(Gb, Gc, Ga, Ge);
    dd2 A22 = ddcof2(Ga, Gd, Gb, Gb);

    dd2 md0 = sum3dd2(ddmulf2(A00, Bx), ddmulf2(A01, By), ddmulf2(A02, Bz));
    dd2 md1 = sum3dd2(ddmulf2(A01, Bx), ddmulf2(A11, By), ddmulf2(A12, Bz));
    dd2 md2 = sum3dd2(ddmulf2(A02, Bx), ddmulf2(A12, By), ddmulf2(A22, Bz));

    ull m0p = add2(md0.hi, md0.lo);
    ull m1p = add2(md1.hi, md1.lo);
    ull m2p = add2(md2.hi, md2.lo);

    ull nnp = mul2(m0p, m0p);
    nnp = fma2(m1p, m1p, nnp);
    nnp = fma2(m2p, m2p, nnp);

    float m0_0, m0_1; unpack2(m0p, m0_0, m0_1);
    float m1_0, m1_1; unpack2(m1p, m1_0, m1_1);
    float m2_0, m2_1; unpack2(m2p, m2_0, m2_1);
    float nn0, nn1;   unpack2(nnp, nn0, nn1);

    float norm0 = sqrtf(nn0); if (norm0 == 0.0f) norm0 = 1e-4f;
    float norm1 = sqrtf(nn1); if (norm1 == 0.0f) norm1 = 1e-4f;

    const int gi = i0 + 2 * ty;
    const int gj = j0 + tx;
    size_t base = (size_t)bb * 3 * (HH * WW) + (size_t)gi * WW + gj;
    out[base]               = __fdiv_rn(-m0_0, norm0);
    out[base +     HH * WW] = __fdiv_rn(-m1_0, norm0);
    out[base + 2 * HH * WW] = __fdiv_rn(-m2_0, norm0);
    base += WW;   // next row, pixel 1
    out[base]               = __fdiv_rn(-m0_1, norm1);
    out[base +     HH * WW] = __fdiv_rn(-m1_1, norm1);
    out[base + 2 * HH * WW] = __fdiv_rn(-m2_1, norm1);
}

extern "C" void kernel_launch(void* const* d_in, const int* in_sizes, int n_in,
                              void* d_out, int out_size) {
    const float* depth = (const float*)d_in[0];
    float* out = (float*)d_out;

    rays_kernel<<<(WW + HH + 255) / 256, 256>>>();

    dim3 block(BW, TY, 1);
    dim3 grid(WW / BW, HH / TH, BATCH);
    normals_kernel<<<grid, block>>>(depth, out);
}